// round 13
// baseline (speedup 1.0000x reference)
#include <cuda_runtime.h>
#include <cuda_bf16.h>
#include <cstdint>

#define N_ATOMS 100000
#define N_PAIRS 6400000
#define LOG2E 1.4426950408889634f

struct ZParams {
    float cbase;
    float ca, cb, cc;
    float ga, gb, gc;
};
__device__ ZParams g_params;
__device__ float2 g_tbl_i[N_ATOMS];   // {Z*atom_mask, Z^|a_exp|}
__device__ float2 g_tbl_j[N_ATOMS];   // {Z,           Z^|a_exp|}

__device__ __forceinline__ float ex2a(float x) {
    float r; asm("ex2.approx.f32 %0, %1;" : "=f"(r) : "f"(x)); return r;
}
__device__ __forceinline__ float lg2a(float x) {
    float r; asm("lg2.approx.f32 %0, %1;" : "=f"(r) : "f"(x)); return r;
}
__device__ __forceinline__ float rsqa(float x) {
    float r; asm("rsqrt.approx.f32 %0, %1;" : "=f"(r) : "f"(x)); return r;
}
__device__ __forceinline__ uint32_t smem_u32(const void* p) {
    uint32_t a;
    asm("{ .reg .u64 t; cvta.to.shared.u64 t, %1; cvt.u32.u64 %0, t; }"
        : "=r"(a) : "l"(p));
    return a;
}
__device__ __forceinline__ void bulk_g2s(uint32_t smem_addr, const void* gmem,
                                         uint32_t bytes, uint32_t mbar) {
    asm volatile(
        "cp.async.bulk.shared::cta.global.mbarrier::complete_tx::bytes "
        "[%0], [%1], %2, [%3];"
        :: "r"(smem_addr), "l"(gmem), "r"(bytes), "r"(mbar) : "memory");
}
__device__ __forceinline__ void mbar_init(uint32_t mbar, uint32_t count) {
    asm volatile("mbarrier.init.shared.b64 [%0], %1;" :: "r"(mbar), "r"(count) : "memory");
}
__device__ __forceinline__ void mbar_expect_tx(uint32_t mbar, uint32_t bytes) {
    asm volatile("mbarrier.arrive.expect_tx.shared.b64 _, [%0], %1;"
                 :: "r"(mbar), "r"(bytes) : "memory");
}
__device__ __forceinline__ void mbar_wait(uint32_t mbar, uint32_t parity) {
    asm volatile(
        "{\n\t"
        ".reg .pred P;\n\t"
        "WAIT_%=:\n\t"
        "mbarrier.try_wait.parity.acquire.cta.shared::cta.b64 P, [%0], %1, 0x989680;\n\t"
        "@!P bra WAIT_%=;\n\t"
        "}"
        :: "r"(mbar), "r"(parity) : "memory");
}

__global__ void prep_kernel(const float* __restrict__ Z,
                            const float* __restrict__ amask,
                            const float* __restrict__ a_coef,
                            const float* __restrict__ a_exp,
                            const float* __restrict__ pc,
                            const float* __restrict__ pe,
                            float* __restrict__ out)
{
    int tid = blockIdx.x * blockDim.x + threadIdx.x;
    float aexp = fabsf(a_exp[0]);
    for (int i = tid; i < N_ATOMS; i += gridDim.x * blockDim.x) {
        float z = Z[i];
        float za = ex2a(aexp * lg2a(z));   // z^aexp, z in [1,94] > 0
        g_tbl_i[i] = make_float2(z * amask[i], za);
        g_tbl_j[i] = make_float2(z, za);
        out[i] = 0.0f;
    }
    if (tid == 0) {
        float c[4], e[4];
        float m = -1e30f;
        #pragma unroll
        for (int k = 0; k < 4; k++) {
            c[k] = fabsf(pc[k]);
            e[k] = fabsf(pe[k]);
            if (c[k] > m) m = c[k];
        }
        float sum = 0.0f, w[4];
        #pragma unroll
        for (int k = 0; k < 4; k++) { w[k] = expf(c[k] - m); sum += w[k]; }
        #pragma unroll
        for (int k = 0; k < 4; k++) w[k] /= sum;
        int kmin = 0;
        #pragma unroll
        for (int k = 1; k < 4; k++) if (e[k] < e[kmin]) kmin = k;
        float acoef = fabsf(a_coef[0]);
        float scale = -LOG2E / acoef;
        ZParams p;
        p.cbase = w[kmin];
        float* cs = &p.ca;
        float* gs = &p.ga;
        int n = 0;
        for (int k = 0; k < 4; k++) {
            if (k == kmin) continue;
            cs[n] = w[k];
            gs[n] = (e[k] - e[kmin]) * scale;
            n++;
        }
        g_params = p;
    }
}

#define TPB   256
#define CHUNK 512          // pairs per block (2 per thread)
#define CHUNK_BYTES (CHUNK * 24u)   // 12 disp + 4 ii + 4 jj + 4 bm

__global__ void __launch_bounds__(TPB, 8) pair_kernel(
    const float* __restrict__ disp,
    const int*   __restrict__ idx_i,
    const int*   __restrict__ idx_j,
    const float* __restrict__ bmask,
    float*       __restrict__ out)
{
    __shared__ alignas(16) float sdisp[CHUNK * 3];
    __shared__ alignas(16) int   sii[CHUNK];
    __shared__ alignas(16) int   sjj[CHUNK];
    __shared__ alignas(16) float sbm[CHUNK];
    __shared__ alignas(8)  unsigned long long mbar_storage;

    const uint32_t mb = smem_u32(&mbar_storage);
    const size_t base = (size_t)blockIdx.x * CHUNK;
    const unsigned lane = threadIdx.x & 31u;

    if (threadIdx.x == 0) {
        mbar_init(mb, 1);
        asm volatile("fence.proxy.async.shared::cta;" ::: "memory");
    }
    __syncthreads();

    if (threadIdx.x == 0) {
        mbar_expect_tx(mb, CHUNK_BYTES);
        bulk_g2s(smem_u32(sdisp), disp + base * 3, CHUNK * 12u, mb);
        bulk_g2s(smem_u32(sii),   idx_i + base,    CHUNK * 4u,  mb);
        bulk_g2s(smem_u32(sjj),   idx_j + base,    CHUNK * 4u,  mb);
        bulk_g2s(smem_u32(sbm),   bmask + base,    CHUNK * 4u,  mb);
    }
    mbar_wait(mb, 0);

    const int q0 = 2 * threadIdx.x;
    const int q1 = q0 + 1;

    // indices + gathers first (long-latency, L1 now dedicated to tables)
    int i0 = sii[q0], i1 = sii[q1];
    int j0 = sjj[q0], j1 = sjj[q1];
    float2 tj0 = g_tbl_j[j0];
    float2 tj1 = g_tbl_j[j1];
    float2 ti0 = g_tbl_i[i0];
    float2 ti1 = g_tbl_i[i1];

    float xs[2] = {sdisp[3 * q0 + 0], sdisp[3 * q1 + 0]};
    float ys[2] = {sdisp[3 * q0 + 1], sdisp[3 * q1 + 1]};
    float zs[2] = {sdisp[3 * q0 + 2], sdisp[3 * q1 + 2]};
    float bs[2] = {sbm[q0], sbm[q1]};
    float2 ti[2] = {ti0, ti1};
    float2 tj[2] = {tj0, tj1};

    ZParams p = g_params;

    float vs[2];
    #pragma unroll
    for (int m = 0; m < 2; m++) {
        float x = xs[m], y = ys[m], z = zs[m];
        float r2 = fmaf(x, x, fmaf(y, y, z * z));
        r2 = fmaxf(r2, 1e-20f);
        float rinv = rsqa(r2);
        float d = r2 * rinv;               // d = sqrt(r2), rinv = 1/d

        float s  = fmaxf(ti[m].y + tj[m].y, 1e-10f);
        float ds = d * s;
        float ea = ex2a(p.ga * ds);
        float eb = ex2a(p.gb * ds);
        float ec = ex2a(p.gc * ds);
        float phi = fmaf(p.ca, ea, fmaf(p.cb, eb, fmaf(p.cc, ec, p.cbase)));

        float xq = 5.0f - d;
        float poly = fmaf(fmaf(6.0f, xq, -15.0f), xq, 10.0f) * (xq * xq * xq);
        float sw = (d < 4.0f) ? 1.0f : ((d < 5.0f) ? poly : 0.0f);

        vs[m] = 0.5f * ti[m].x * tj[m].x * phi * sw * bs[m] * rinv;
    }

    // merge the two pairs if same key, else flush the first
    float acc;
    int   key;
    if (i0 == i1) {
        acc = vs[0] + vs[1];
        key = i0;
    } else {
        if (vs[0] != 0.0f) atomicAdd(&out[i0], vs[0]);
        acc = vs[1];
        key = i1;
    }

    // warp segmented suffix-sum by key (keys non-decreasing by lane)
    float v = acc;
    int   k = key;
    #pragma unroll
    for (int off = 1; off < 32; off <<= 1) {
        int   kn = __shfl_down_sync(0xFFFFFFFFu, k, off);
        float vn = __shfl_down_sync(0xFFFFFFFFu, v, off);
        if (lane + off < 32 && kn == k) v += vn;
    }
    int kprev = __shfl_up_sync(0xFFFFFFFFu, k, 1);
    bool head = (lane == 0) || (kprev != k);
    if (head && v != 0.0f) atomicAdd(&out[k], v);
}

extern "C" void kernel_launch(void* const* d_in, const int* in_sizes, int n_in,
                              void* d_out, int out_size)
{
    const float* Z     = (const float*)d_in[0];
    const float* disp  = (const float*)d_in[1];
    const int*   idx_i = (const int*)d_in[2];
    const int*   idx_j = (const int*)d_in[3];
    const float* amask = (const float*)d_in[4];
    const float* bmask = (const float*)d_in[6];
    const float* acoef = (const float*)d_in[n_in - 4];
    const float* aexp  = (const float*)d_in[n_in - 3];
    const float* pc    = (const float*)d_in[n_in - 2];
    const float* pe    = (const float*)d_in[n_in - 1];
    float* out = (float*)d_out;

    (void)in_sizes; (void)out_size;

    prep_kernel<<<800, 128>>>(Z, amask, acoef, aexp, pc, pe, out);

    pair_kernel<<<N_PAIRS / CHUNK, TPB>>>(disp, idx_i, idx_j, bmask, out);
}